// round 1
// baseline (speedup 1.0000x reference)
#include <cuda_runtime.h>
#include <math.h>

#define D_DIM 1024
#define B_DIM 8
#define T_DIM 1024
#define EPC 8            // e-rows per CTA in scan
#define NCTA 128
#define SROW 1028        // padded smem row stride in floats (stagger banks)
#define SPECTRAL_RADIUS 0.999f
#define EPS_F 1e-8f

// ------------------------- device scratch (no allocs allowed) ----------------
__device__ float g_p[6][D_DIM];     // unnormalized power-iteration vectors p1..p6
__device__ float g_scale;           // final multiplier applied to W
__device__ int   g_cnt[T_DIM];      // per-step completion counters (reset per launch)

// ------------------------- power iteration matvecs ---------------------------
// out[d] = sum_e W[e,d] * in[e]   (W^T * in). Grid 128 x 256. 8 outputs/block.
__global__ void mv_T_kernel(const float* __restrict__ W, const float* __restrict__ vin,
                            float* __restrict__ vout) {
    int dl = threadIdx.x >> 5;          // 0..7
    int lane = threadIdx.x & 31;
    int d = blockIdx.x * 8 + dl;
    float acc = 0.f;
    for (int e = lane; e < D_DIM; e += 32)
        acc += W[(size_t)e * D_DIM + d] * vin[e];
    #pragma unroll
    for (int off = 16; off; off >>= 1)
        acc += __shfl_down_sync(0xffffffffu, acc, off);
    if (lane == 0) vout[d] = acc;
}

// out[e] = sum_d W[e,d] * in[d]   (W * in). Grid 128 x 256. 8 outputs/block.
__global__ void mv_N_kernel(const float* __restrict__ W, const float* __restrict__ vin,
                            float* __restrict__ vout) {
    int el = threadIdx.x >> 5;
    int lane = threadIdx.x & 31;
    int e = blockIdx.x * 8 + el;
    float acc = 0.f;
    const float* row = W + (size_t)e * D_DIM;
    for (int d = lane; d < D_DIM; d += 32)
        acc += row[d] * vin[d];
    #pragma unroll
    for (int off = 16; off; off >>= 1)
        acc += __shfl_down_sync(0xffffffffu, acc, off);
    if (lane == 0) vout[e] = acc;
}

// Reduce norms of p1..p6 and run the scalar normalization chain.
__global__ void finalize_kernel() {
    __shared__ float red[256];
    __shared__ float ssq[6];
    int tid = threadIdx.x;
    for (int v = 0; v < 6; v++) {
        float local = 0.f;
        for (int i = tid; i < D_DIM; i += 256) {
            float x = g_p[v][i];
            local += x * x;
        }
        red[tid] = local;
        __syncthreads();
        for (int s = 128; s; s >>= 1) {
            if (tid < s) red[tid] += red[tid + s];
            __syncthreads();
        }
        if (tid == 0) ssq[v] = red[0];
        __syncthreads();
    }
    if (tid == 0) {
        // v1 = a1*p1, u1 = b1*p2, v2 = a2*p3, u2 = b2*p4, v3 = a3*p5, u3 = b3*p6
        float a1 = 1.f / (sqrtf(ssq[0]) + EPS_F);
        float b1 = a1 / (a1 * sqrtf(ssq[1]) + EPS_F);
        float a2 = b1 / (b1 * sqrtf(ssq[2]) + EPS_F);
        float b2 = a2 / (a2 * sqrtf(ssq[3]) + EPS_F);
        float a3 = b2 / (b2 * sqrtf(ssq[4]) + EPS_F);
        float b3 = a3 / (a3 * sqrtf(ssq[5]) + EPS_F);
        float sigma = fabsf(a3 * b3 * ssq[5]);   // u3 . (W v3) = a3*b3*||p6||^2
        g_scale = SPECTRAL_RADIUS / (sigma + EPS_F);
    }
}

// ------------------------- persistent sequential scan ------------------------
// h_t = W_eff (x_t + h_{t-1}) + b ; out[t] = silu(h_t) ; h buffer holds h[0..T].
__global__ void __launch_bounds__(256, 1)
scan_kernel(const float* __restrict__ x, const float* __restrict__ W,
            const float* __restrict__ bias, float* __restrict__ out_silu,
            float* __restrict__ out_h) {
    extern __shared__ float sm[];
    float* w_s   = sm;                       // EPC * SROW
    float* s_s   = sm + EPC * SROW;          // B_DIM * SROW
    float* red_s = sm + 2 * EPC * SROW;      // 4 tiles * 2 warps * 16
    __shared__ float bias_s[EPC];

    int tid = threadIdx.x;
    int e0 = blockIdx.x * EPC;
    float scale = g_scale;

    // Preload this CTA's W rows, pre-scaled.
    for (int idx = tid; idx < EPC * (D_DIM / 4); idx += 256) {
        int r = idx >> 8;            // D/4 = 256 float4 per row
        int c4 = idx & 255;
        float4 w4 = ((const float4*)(W + (size_t)(e0 + r) * D_DIM))[c4];
        w4.x *= scale; w4.y *= scale; w4.z *= scale; w4.w *= scale;
        *(float4*)(w_s + r * SROW + c4 * 4) = w4;
    }
    if (tid < EPC) bias_s[tid] = bias[e0 + tid];
    __syncthreads();

    int tile = tid >> 6;             // 0..3
    int l64 = tid & 63;              // d-lane within tile
    int bt = (tile & 1) * 4;         // batch-tile base
    int et = (tile >> 1) * 4;        // e-tile base
    int warp_in_tile = (tid >> 5) & 1;

    for (int t = 0; t < T_DIM; ++t) {
        if (t > 0) {
            if (tid == 0) {
                volatile int* c = g_cnt + (t - 1);
                while (*c != NCTA) { }
                __threadfence();
            }
            __syncthreads();
        }
        // Stage s = x[t] + h[t] into smem.
        const float4* xp = (const float4*)(x + (size_t)t * B_DIM * D_DIM);
        const float4* hp = (const float4*)(out_h + (size_t)t * B_DIM * D_DIM);
        for (int idx = tid; idx < B_DIM * (D_DIM / 4); idx += 256) {
            int r = idx >> 8;
            int c4 = idx & 255;
            float4 xv = xp[idx];
            float4 hv = hp[idx];
            xv.x += hv.x; xv.y += hv.y; xv.z += hv.z; xv.w += hv.w;
            *(float4*)(s_s + r * SROW + c4 * 4) = xv;
        }
        __syncthreads();

        // 4x4 register-tiled partial dot products; lanes cover contiguous 16B
        // (conflict-free), strided by 256 floats between k-iterations.
        float acc[4][4];
        #pragma unroll
        for (int i = 0; i < 4; i++)
            #pragma unroll
            for (int j = 0; j < 4; j++) acc[i][j] = 0.f;

        #pragma unroll
        for (int k = 0; k < 4; ++k) {
            int d = l64 * 4 + k * 256;
            float4 sv[4], wv[4];
            #pragma unroll
            for (int i = 0; i < 4; i++) sv[i] = *(const float4*)(s_s + (bt + i) * SROW + d);
            #pragma unroll
            for (int j = 0; j < 4; j++) wv[j] = *(const float4*)(w_s + (et + j) * SROW + d);
            #pragma unroll
            for (int i = 0; i < 4; i++)
                #pragma unroll
                for (int j = 0; j < 4; j++)
                    acc[i][j] += sv[i].x * wv[j].x + sv[i].y * wv[j].y +
                                 sv[i].z * wv[j].z + sv[i].w * wv[j].w;
        }
        // Warp reduction over d-lanes.
        #pragma unroll
        for (int i = 0; i < 4; i++)
            #pragma unroll
            for (int j = 0; j < 4; j++) {
                float v = acc[i][j];
                #pragma unroll
                for (int off = 16; off; off >>= 1)
                    v += __shfl_down_sync(0xffffffffu, v, off);
                acc[i][j] = v;
            }
        if ((tid & 31) == 0) {
            #pragma unroll
            for (int i = 0; i < 4; i++)
                #pragma unroll
                for (int j = 0; j < 4; j++)
                    red_s[tile * 32 + warp_in_tile * 16 + i * 4 + j] = acc[i][j];
        }
        __syncthreads();

        if (tid < 64) {
            int tl = tid >> 4;
            int ij = tid & 15;
            float v = red_s[tl * 32 + ij] + red_s[tl * 32 + 16 + ij];
            int i = ij >> 2, j = ij & 3;
            int b = (tl & 1) * 4 + i;
            int el = (tl >> 1) * 4 + j;
            float h = v + bias_s[el];
            size_t off = (size_t)t * B_DIM * D_DIM + (size_t)b * D_DIM + e0 + el;
            out_h[off + B_DIM * D_DIM] = h;                 // h[t+1]
            out_silu[off] = h / (1.f + expf(-h));           // silu(h_t)
        }
        __syncthreads();   // all writes issued; red_s safe to reuse
        if (tid == 0) {
            __threadfence();                 // publish h[t+1] grid-wide
            atomicAdd(g_cnt + t, 1);
        }
    }
}

// ------------------------------- launcher ------------------------------------
extern "C" void kernel_launch(void* const* d_in, const int* in_sizes, int n_in,
                              void* d_out, int out_size) {
    const float* x  = (const float*)d_in[0];   // [T, B, D]
    const float* h0 = (const float*)d_in[1];   // [B, D]
    const float* W  = (const float*)d_in[2];   // [D, D]
    const float* bv = (const float*)d_in[3];   // [D]
    const float* u  = (const float*)d_in[4];   // [D]

    float* out_silu = (float*)d_out;                               // [T, B, D]
    float* out_h    = (float*)d_out + (size_t)T_DIM * B_DIM * D_DIM; // [T+1, B, D]

    // Reset step counters (captured as a memset node each replay).
    void* cnt_addr = nullptr;
    cudaGetSymbolAddress(&cnt_addr, g_cnt);
    cudaMemsetAsync(cnt_addr, 0, sizeof(int) * T_DIM, 0);

    // h[0] = h0
    cudaMemcpyAsync(out_h, h0, sizeof(float) * B_DIM * D_DIM,
                    cudaMemcpyDeviceToDevice, 0);

    // Power iteration: p1..p6 unnormalized, scalar chain in finalize.
    float* p = nullptr;
    cudaGetSymbolAddress((void**)&p, g_p);
    mv_T_kernel<<<128, 256>>>(W, u, p + 0 * D_DIM);
    mv_N_kernel<<<128, 256>>>(W, p + 0 * D_DIM, p + 1 * D_DIM);
    mv_T_kernel<<<128, 256>>>(W, p + 1 * D_DIM, p + 2 * D_DIM);
    mv_N_kernel<<<128, 256>>>(W, p + 2 * D_DIM, p + 3 * D_DIM);
    mv_T_kernel<<<128, 256>>>(W, p + 3 * D_DIM, p + 4 * D_DIM);
    mv_N_kernel<<<128, 256>>>(W, p + 4 * D_DIM, p + 5 * D_DIM);
    finalize_kernel<<<1, 256>>>();

    // Persistent sequential scan.
    size_t smem = (size_t)(2 * EPC * SROW + 128) * sizeof(float);
    cudaFuncSetAttribute(scan_kernel, cudaFuncAttributeMaxDynamicSharedMemorySize,
                         (int)smem);
    scan_kernel<<<NCTA, 256, smem>>>(x, W, bv, out_silu, out_h);
}